// round 9
// baseline (speedup 1.0000x reference)
#include <cuda_runtime.h>
#include <cstdint>

// out[o*256+k][h][m] = sum_{i,j} w[i][k][j] * xp[m+j], xp = padded/rolled row.
// Grid 112 = (o:2, kq:4, h:14). Block 512 = 16 warps; warp g owns i in [16g,16g+16).
// Lane covers adjacent channels k0=kq*64+2*lane, k0+1 packed in f32x2 lanes.
// Per-warp-private smem staging (no block barriers in mainloop):
//   weights: u64 SW[g][il][j][lane]   (16*16*3*32 u64 = 192KB)  - self staged/read
//   xdup:    u64 SX[g][il][a]         (16*16*16    u64 =  32KB) - {v,v} duplicated
// Mainloop: 3 LDS.64 + 8 LDS.128 + 42 FFMA2 per il; zero MOV repacks.
// One __syncthreads before the deterministic cross-warp smem reduction.

#define W_U64 (16 * 16 * 3 * 32)          // 24576 u64 = 192KB
#define X_U64 (16 * 16 * 16)              // 4096 u64 = 32KB
#define SMEM_BYTES ((W_U64 + X_U64) * 8)  // 229376 = 224KB

extern __shared__ uint64_t smemu[];

__device__ __forceinline__ uint64_t pkab(float a, float b) {
    uint64_t r;
    asm("mov.b64 %0, {%1, %2};" : "=l"(r)
        : "r"(__float_as_uint(a)), "r"(__float_as_uint(b)));
    return r;
}
__device__ __forceinline__ uint64_t ffma2(uint64_t a, uint64_t b, uint64_t c) {
    uint64_t d;
    asm("fma.rn.f32x2 %0, %1, %2, %3;" : "=l"(d) : "l"(a), "l"(b), "l"(c));
    return d;
}

__global__ __launch_bounds__(512, 1)
void fused_conv_kernel(const float* __restrict__ x,
                       const float* __restrict__ w,
                       float* __restrict__ out) {
    const int bx = blockIdx.x;           // 0..111
    const int o  = bx / 56;
    const int kq = (bx / 14) & 3;
    const int h  = bx % 14;
    const int tid  = threadIdx.x;
    const int g    = tid >> 5;           // warp / i-group 0..15
    const int lane = tid & 31;
    const int n    = (h + 13) % 14;      // undo roll along H
    const int ibase = g * 16;
    const int k0 = kq * 64 + 2 * lane;   // this lane's even channel (within o-group)

    uint64_t* swu = smemu;               // SW[g][il][j][lane]
    uint64_t* sxd = smemu + W_U64;       // SX[g][il][a]

    // ---- stage x (duplicated pairs), per-warp private ----
    // xp[a] = (a in [1,14]) ? x[(o*256 + i)*196 + n*14 + (a+12)%14] : 0
    {
        const float* xb = x + ((size_t)o * 256 + ibase) * 196 + n * 14;
#pragma unroll
        for (int r = 0; r < 8; r++) {
            const int idx = r * 32 + lane;       // 0..255
            const int il = idx >> 4;
            const int a  = idx & 15;
            float v = 0.f;
            if (a >= 1 && a <= 14) v = xb[(size_t)il * 196 + (a + 12) % 14];
            sxd[g * 256 + idx] = pkab(v, v);
        }
    }

    // ---- stage weights, per-warp private, lane-self slots ----
    // w[i][k][j] at (i*256+k)*3 + j ; lane loads 6 floats for (k0, k0+1), repacks
    // to {w[k0][j], w[k0+1][j]} and stores SW[g][il][j][lane].
    {
        const float* wp0 = w + ((size_t)(ibase)*256 + k0) * 3;
#pragma unroll
        for (int il = 0; il < 16; il++) {
            const float* wp = wp0 + (size_t)il * 768;
            const float2 A = *(const float2*)(wp);       // a0 a1
            const float2 B = *(const float2*)(wp + 2);   // a2 b0
            const float2 C = *(const float2*)(wp + 4);   // b1 b2
            const size_t base = ((size_t)(g * 16 + il) * 3) * 32 + lane;
            swu[base]      = pkab(A.x, B.y);   // {a0, b0}
            swu[base + 32] = pkab(A.y, C.x);   // {a1, b1}
            swu[base + 64] = pkab(B.x, C.y);   // {a2, b2}
        }
    }
    __syncwarp();

    // ---- mainloop: zero barriers, zero movs ----
    uint64_t acc[14];
#pragma unroll
    for (int m = 0; m < 14; m++) acc[m] = 0ull;

#pragma unroll
    for (int il = 0; il < 16; il++) {
        const uint64_t* wrow = swu + ((size_t)(g * 16 + il) * 3) * 32 + lane;
        const uint64_t W0 = wrow[0];
        const uint64_t W1 = wrow[32];
        const uint64_t W2 = wrow[64];

        const ulonglong2* xd = (const ulonglong2*)(sxd + g * 256 + il * 16);
        uint64_t X[16];
#pragma unroll
        for (int t = 0; t < 8; t++) {        // 8 broadcast LDS.128
            const ulonglong2 v = xd[t];
            X[2 * t] = v.x;
            X[2 * t + 1] = v.y;
        }

#pragma unroll
        for (int m = 0; m < 14; m++) {
            acc[m] = ffma2(W0, X[m],     acc[m]);
            acc[m] = ffma2(W1, X[m + 1], acc[m]);
            acc[m] = ffma2(W2, X[m + 2], acc[m]);
        }
    }

    // ---- cross-warp reduction (reuse weight region) ----
    __syncthreads();                      // everyone done with SW reads
    uint64_t* ps = smemu;                 // ps[(g*32 + lane)*14 + m]
#pragma unroll
    for (int m = 0; m < 14; m++)
        ps[((size_t)(g * 32 + lane)) * 14 + m] = acc[m];
    __syncthreads();

    if (tid < 448) {
        const int lk = tid / 14;          // lane-pair index 0..31
        const int m  = tid % 14;
        float lo = 0.f, hi = 0.f;
#pragma unroll
        for (int gg = 0; gg < 16; gg++) { // fixed order -> deterministic
            const float2 v = ((const float2*)ps)[(gg * 32 + lk) * 14 + m];
            lo += v.x;
            hi += v.y;
        }
        const int cg = o * 256 + kq * 64 + 2 * lk;
        out[(size_t)cg * 196 + h * 14 + m] = lo;
        out[(size_t)(cg + 1) * 196 + h * 14 + m] = hi;
    }
}

extern "C" void kernel_launch(void* const* d_in, const int* in_sizes, int n_in,
                              void* d_out, int out_size) {
    const float* x = (const float*)d_in[0];   // (1,512,14,14)
    const float* w = (const float*)d_in[1];   // (256,256,3)
    float* out = (float*)d_out;

    cudaFuncSetAttribute(fused_conv_kernel,
                         cudaFuncAttributeMaxDynamicSharedMemorySize, SMEM_BYTES);
    fused_conv_kernel<<<112, 512, SMEM_BYTES>>>(x, w, out);
}